// round 9
// baseline (speedup 1.0000x reference)
#include <cuda_runtime.h>
#include <math.h>

#define Bsz 4096
#define V 2000
#define VP 2048
#define KT 50
#define KP 64
#define HID 500
#define EMB 300

#define NBLK 128
#define RPB 16        // rows per block
#define NG 32         // K-groups per block (16 threads each -> 512 threads)
#define GK 64         // K range per group
#define CH 16         // chunk of K per smem stage
#define VS_STR 72     // padded Vs row stride
#define SM_FLOATS (NG*CH*16 + NG*CH*VS_STR)   // 8192 + 36864 = 45056 floats (180224 B)

// ---------------- scratch (device globals; no runtime alloc) ----------------
__device__ float g_h1[Bsz*HID];
__device__ float g_h2[Bsz*HID];
__device__ float g_mulin[Bsz*KP];
__device__ float g_lvlin[Bsz*KP];
__device__ float g_theta[Bsz*KP];
__device__ float g_Y[Bsz*V];
__device__ float g_rowloss_a[Bsz];
__device__ float g_rowloss_b[Bsz];
__device__ float g_mmean[KP]; __device__ float g_mrstd[KP];
__device__ float g_lmean[KP]; __device__ float g_lrstd[KP];
__device__ float g_ymean[VP]; __device__ float g_yrstd[VP];
__device__ float g_na[V*EMB]; __device__ float g_nb[V*EMB];
__device__ float g_Km[VP*VP];
__device__ float g_KmT[VP*VP];
__device__ float g_KM[VP*VP];
__device__ float g_a[VP*KP]; __device__ float g_b[VP*KP];
__device__ float g_u[VP*KP]; __device__ float g_v[VP*KP];
__device__ float g_red[NBLK];
__device__ unsigned g_bar_cnt;
__device__ unsigned g_bar_gen;

// ---------------- f32x2 packed helpers ----------------
__device__ __forceinline__ unsigned long long pack2(float x) {
    unsigned long long r;
    asm("mov.b64 %0, {%1, %1};" : "=l"(r) : "f"(x));
    return r;
}
__device__ __forceinline__ void ffma2(unsigned long long& d,
                                      unsigned long long a, unsigned long long b) {
    asm("fma.rn.f32x2 %0, %1, %2, %0;" : "+l"(d) : "l"(a), "l"(b));
}
__device__ __forceinline__ float lo32(unsigned long long a) {
    return __uint_as_float((unsigned)(a & 0xffffffffULL));
}
__device__ __forceinline__ float hi32(unsigned long long a) {
    return __uint_as_float((unsigned)(a >> 32));
}

// ---------------- generic NN SGEMM: C = act(A@B + bias) ----------------
__global__ __launch_bounds__(256) void sgemm_nn(
    const float* __restrict__ A, const float* __restrict__ B,
    const float* __restrict__ bias, float* __restrict__ C,
    int M, int N, int K, int lda, int ldb, int ldc, int act)
{
    __shared__ float As[16][68];
    __shared__ float Bs[16][68];
    int tid = threadIdx.x;
    int tx = tid & 15, ty = tid >> 4;
    int row0 = blockIdx.y * 64, col0 = blockIdx.x * 64;
    float acc[4][4];
    #pragma unroll
    for (int i = 0; i < 4; i++)
        #pragma unroll
        for (int j = 0; j < 4; j++) acc[i][j] = 0.f;

    for (int k0 = 0; k0 < K; k0 += 16) {
        #pragma unroll
        for (int s = 0; s < 4; s++) {
            int idx = tid + s * 256;
            int m = idx >> 4, kk = idx & 15;
            int gr = row0 + m, gk = k0 + kk;
            As[kk][m] = (gr < M && gk < K) ? A[(size_t)gr * lda + gk] : 0.f;
        }
        #pragma unroll
        for (int s = 0; s < 4; s++) {
            int idx = tid + s * 256;
            int kk = idx >> 6, n = idx & 63;
            int gk = k0 + kk, gc = col0 + n;
            Bs[kk][n] = (gk < K && gc < N) ? B[(size_t)gk * ldb + gc] : 0.f;
        }
        __syncthreads();
        #pragma unroll
        for (int kk = 0; kk < 16; kk++) {
            float ra[4], rb[4];
            #pragma unroll
            for (int i = 0; i < 4; i++) ra[i] = As[kk][ty * 4 + i];
            #pragma unroll
            for (int j = 0; j < 4; j++) rb[j] = Bs[kk][tx * 4 + j];
            #pragma unroll
            for (int i = 0; i < 4; i++)
                #pragma unroll
                for (int j = 0; j < 4; j++)
                    acc[i][j] = fmaf(ra[i], rb[j], acc[i][j]);
        }
        __syncthreads();
    }
    #pragma unroll
    for (int i = 0; i < 4; i++) {
        int gr = row0 + ty * 4 + i;
        if (gr >= M) continue;
        #pragma unroll
        for (int j = 0; j < 4; j++) {
            int gc = col0 + tx * 4 + j;
            if (gc >= N) continue;
            float vv = acc[i][j];
            if (bias) vv += bias[gc];
            if (act) vv = fmaxf(vv, 0.f) + log1pf(expf(-fabsf(vv)));
            C[(size_t)gr * ldc + gc] = vv;
        }
    }
}

// ---------------- persistent Sinkhorn ----------------
__device__ __forceinline__ void grid_barrier() {
    __syncthreads();
    if (threadIdx.x == 0) {
        __threadfence();
        unsigned gen = *(volatile unsigned*)&g_bar_gen;
        if (atomicAdd(&g_bar_cnt, 1u) == NBLK - 1u) {
            *(volatile unsigned*)&g_bar_cnt = 0u;
            __threadfence();
            *(volatile unsigned*)&g_bar_gen = gen + 1u;
        } else {
            while (*(volatile unsigned*)&g_bar_gen == gen) __nanosleep(32);
        }
        __threadfence();
    }
    __syncthreads();
}

// acc2[8][4] (f32x2 pairs) += A[rows r0..r0+16) x x[.,64], K split across 32 groups
__device__ __forceinline__ void tile_mm2(
    const float* __restrict__ A, const float* __restrict__ x,
    float* As, float* Vs, int r0, int g, int lt, int rowtile, int coltile,
    unsigned long long acc2[8][4])
{
    #pragma unroll
    for (int c = 0; c < GK / CH; c++) {
        int k0 = g * GK + c * CH;
        const float4* arow = (const float4*)&A[(size_t)(r0 + lt) * VP + k0];
        #pragma unroll
        for (int q = 0; q < 4; q++) {
            float4 v4 = __ldg(arow + q);
            As[(q * 4 + 0) * 16 + lt] = v4.x;
            As[(q * 4 + 1) * 16 + lt] = v4.y;
            As[(q * 4 + 2) * 16 + lt] = v4.z;
            As[(q * 4 + 3) * 16 + lt] = v4.w;
        }
        const float4* xrow = (const float4*)&x[(size_t)(k0 + lt) * KP];
        float4* vdst = (float4*)&Vs[lt * VS_STR];
        #pragma unroll
        for (int q = 0; q < 16; q++) vdst[q] = __ldcg(xrow + q);
        __syncthreads();
        #pragma unroll
        for (int kk = 0; kk < CH; kk++) {
            float4 a0 = *(const float4*)&As[kk * 16 + rowtile * 8];
            float4 a1 = *(const float4*)&As[kk * 16 + rowtile * 8 + 4];
            const ulonglong2* bp = (const ulonglong2*)&Vs[kk * VS_STR + coltile * 8];
            ulonglong2 b01 = bp[0], b23 = bp[1];
            unsigned long long rb[4] = {b01.x, b01.y, b23.x, b23.y};
            float ra[8] = {a0.x, a0.y, a0.z, a0.w, a1.x, a1.y, a1.z, a1.w};
            #pragma unroll
            for (int i = 0; i < 8; i++) {
                unsigned long long ap = pack2(ra[i]);
                #pragma unroll
                for (int j = 0; j < 4; j++) ffma2(acc2[i][j], ap, rb[j]);
            }
        }
        __syncthreads();
    }
}

__device__ __forceinline__ void store_partials2(
    float* red, unsigned long long acc2[8][4], int g, int rowtile, int coltile)
{
    #pragma unroll
    for (int i = 0; i < 8; i++) {
        float4* dst = (float4*)&red[g * 1024 + (rowtile * 8 + i) * 64 + coltile * 8];
        dst[0] = make_float4(lo32(acc2[i][0]), hi32(acc2[i][0]),
                             lo32(acc2[i][1]), hi32(acc2[i][1]));
        dst[1] = make_float4(lo32(acc2[i][2]), hi32(acc2[i][2]),
                             lo32(acc2[i][3]), hi32(acc2[i][3]));
    }
}

__global__ __launch_bounds__(512, 1) void sinkhorn_persist() {
    extern __shared__ float sm[];
    int t = threadIdx.x;
    int g = t >> 4, lt = t & 15;
    int rowtile = lt >> 3, coltile = lt & 7;
    int r0 = blockIdx.x * RPB;
    float* As = sm + g * (CH * 16);
    float* Vs = sm + NG * CH * 16 + g * (CH * VS_STR);
    float* red = sm;  // alias (guarded by __syncthreads)

    for (int half = 0; half < 2 * 500 + 1; half++) {
        bool uh = !(half & 1);
        const float* A = uh ? g_Km : g_KmT;
        const float* x = uh ? g_v : g_u;
        const float* num = uh ? g_a : g_b;
        float* out = uh ? g_u : g_v;

        unsigned long long acc2[8][4];
        #pragma unroll
        for (int i = 0; i < 8; i++)
            #pragma unroll
            for (int j = 0; j < 4; j++) acc2[i][j] = 0ULL;

        tile_mm2(A, x, As, Vs, r0, g, lt, rowtile, coltile, acc2);
        store_partials2(red, acc2, g, rowtile, coltile);
        __syncthreads();
        {
            int oi = t * 2;               // 0..1022, covers 1024 outputs
            float sx = 0.f, sy = 0.f;
            #pragma unroll
            for (int gg = 0; gg < NG; gg++) {
                float2 p = *(const float2*)&red[gg * 1024 + oi];
                sx += p.x; sy += p.y;
            }
            int row = oi >> 6, col = oi & 63;
            float2 nm = *(const float2*)&num[(size_t)(r0 + row) * KP + col];
            float2 uv;
            uv.x = nm.x / (sx + 1e-16f);
            uv.y = nm.y / (sy + 1e-16f);
            *(float2*)&out[(size_t)(r0 + row) * KP + col] = uv;
        }
        __syncthreads();
        grid_barrier();
    }

    // epilogue: s = (Km*M) @ v ; partial cost = sum(u * s) over this block's rows
    unsigned long long acc2[8][4];
    #pragma unroll
    for (int i = 0; i < 8; i++)
        #pragma unroll
        for (int j = 0; j < 4; j++) acc2[i][j] = 0ULL;
    tile_mm2(g_KM, g_v, As, Vs, r0, g, lt, rowtile, coltile, acc2);
    store_partials2(red, acc2, g, rowtile, coltile);
    __syncthreads();
    float part = 0.f;
    {
        int oi = t * 2;
        float sx = 0.f, sy = 0.f;
        #pragma unroll
        for (int gg = 0; gg < NG; gg++) {
            float2 p = *(const float2*)&red[gg * 1024 + oi];
            sx += p.x; sy += p.y;
        }
        int row = oi >> 6, col = oi & 63;
        float2 uu = *(const float2*)&g_u[(size_t)(r0 + row) * KP + col];
        part = fmaf(uu.x, sx, fmaf(uu.y, sy, 0.f));
    }
    __syncthreads();
    red[t] = part; __syncthreads();
    for (int off = 256; off > 0; off >>= 1) {
        if (t < off) red[t] += red[t + off];
        __syncthreads();
    }
    if (t == 0) g_red[blockIdx.x] = red[0];
}

__global__ void init_kernel() {
    int idx = blockIdx.x * 256 + threadIdx.x;
    if (idx == 0) { g_bar_cnt = 0u; g_bar_gen = 0u; }
    g_a[idx] = 0.f; g_b[idx] = 0.f;
    int i = idx >> 6, k = idx & 63;
    g_v[idx] = (i < V && k < KT) ? (1.f / V) : 0.f;
}

// ---------------- per-column softmax over V rows of phi (row-major K x V) ----
__global__ void colsoftmax(const float* __restrict__ phi, float* __restrict__ out) {
    int k = blockIdx.x, t = threadIdx.x;
    const float* col = phi + (size_t)k * V;
    __shared__ float red[256];
    float m = -1e30f;
    for (int i = t; i < V; i += 256) m = fmaxf(m, col[i]);
    red[t] = m; __syncthreads();
    for (int off = 128; off > 0; off >>= 1) {
        if (t < off) red[t] = fmaxf(red[t], red[t + off]);
        __syncthreads();
    }
    float mx = red[0]; __syncthreads();
    float s = 0.f;
    for (int i = t; i < V; i += 256) s += expf(col[i] - mx);
    red[t] = s; __syncthreads();
    for (int off = 128; off > 0; off >>= 1) {
        if (t < off) red[t] += red[t + off];
        __syncthreads();
    }
    float inv = 1.f / red[0];
    for (int i = t; i < V; i += 256) out[i * KP + k] = expf(col[i] - mx) * inv;
}

__global__ void norm_rows(const float* __restrict__ Bm, float* __restrict__ out) {
    int r = blockIdx.x, t = threadIdx.x;
    __shared__ float red[128];
    float s = 0.f;
    for (int e = t; e < EMB; e += 128) { float v = Bm[r * EMB + e]; s = fmaf(v, v, s); }
    red[t] = s; __syncthreads();
    for (int off = 64; off > 0; off >>= 1) {
        if (t < off) red[t] += red[t + off];
        __syncthreads();
    }
    float sc = 1.f / fmaxf(sqrtf(red[0]), 1e-12f);
    for (int e = t; e < EMB; e += 128) out[r * EMB + e] = Bm[r * EMB + e] * sc;
}

__global__ __launch_bounds__(256) void cost_nt(
    const float* __restrict__ na, const float* __restrict__ nb)
{
    __shared__ float As[8][68];
    __shared__ float Bs[8][68];
    int tid = threadIdx.x, tx = tid & 15, ty = tid >> 4;
    int i0 = blockIdx.y * 64, j0 = blockIdx.x * 64;
    float acc[4][4];
    #pragma unroll
    for (int i = 0; i < 4; i++)
        #pragma unroll
        for (int j = 0; j < 4; j++) acc[i][j] = 0.f;

    for (int k0 = 0; k0 < 304; k0 += 8) {
        #pragma unroll
        for (int s = 0; s < 2; s++) {
            int idx = tid + s * 256;
            int m = idx >> 3, kk = idx & 7;
            int gk = k0 + kk;
            int gi = i0 + m;
            As[kk][m] = (gi < V && gk < EMB) ? na[(size_t)gi * EMB + gk] : 0.f;
            int gj = j0 + m;
            Bs[kk][m] = (gj < V && gk < EMB) ? nb[(size_t)gj * EMB + gk] : 0.f;
        }
        __syncthreads();
        #pragma unroll
        for (int kk = 0; kk < 8; kk++) {
            float ra[4], rb[4];
            #pragma unroll
            for (int i = 0; i < 4; i++) ra[i] = As[kk][ty * 4 + i];
            #pragma unroll
            for (int j = 0; j < 4; j++) rb[j] = Bs[kk][tx * 4 + j];
            #pragma unroll
            for (int i = 0; i < 4; i++)
                #pragma unroll
                for (int j = 0; j < 4; j++)
                    acc[i][j] = fmaf(ra[i], rb[j], acc[i][j]);
        }
        __syncthreads();
    }
    #pragma unroll
    for (int i = 0; i < 4; i++) {
        #pragma unroll
        for (int j = 0; j < 4; j++) {
            int gi = i0 + ty * 4 + i, gj = j0 + tx * 4 + j;
            float km = 0.f, kmm = 0.f;
            if (gi < V && gj < V) {
                float m = 1.f - acc[i][j];
                km = expf(-10.f * m);
                kmm = km * m;
            }
            g_Km[(size_t)gi * VP + gj] = km;
            g_KmT[(size_t)gj * VP + gi] = km;
            g_KM[(size_t)gi * VP + gj] = kmm;
        }
    }
}

__global__ void colstats_narrow(const float* __restrict__ X, float* mean, float* rstd) {
    int c = blockIdx.x, t = threadIdx.x;
    __shared__ float s1[256], s2[256];
    float a1 = 0.f, a2 = 0.f;
    for (int r = t; r < Bsz; r += 256) {
        float v = X[r * KP + c];
        a1 += v; a2 = fmaf(v, v, a2);
    }
    s1[t] = a1; s2[t] = a2; __syncthreads();
    for (int off = 128; off > 0; off >>= 1) {
        if (t < off) { s1[t] += s1[t + off]; s2[t] += s2[t + off]; }
        __syncthreads();
    }
    if (t == 0) {
        float m = s1[0] / (float)Bsz;
        mean[c] = m;
        rstd[c] = rsqrtf(s2[0] / (float)Bsz - m * m + 1e-5f);
    }
}

__global__ void theta_kernel(
    const float* __restrict__ mulin, const float* __restrict__ lvlin,
    const float* __restrict__ mbn, const float* __restrict__ lbn,
    const float* __restrict__ eps, float* __restrict__ theta, float* __restrict__ rowloss)
{
    int r = blockIdx.x, k = threadIdx.x;
    __shared__ float red[64];
    const float var2 = 0.98f;
    const float logv2 = -0.0202027073f;
    bool valid = (k < KT);
    float mu = 0.f, lv = 0.f, z = -1e30f;
    if (valid) {
        mu = (mulin[r * KP + k] - g_mmean[k]) * g_mrstd[k] + mbn[k];
        lv = (lvlin[r * KP + k] - g_lmean[k]) * g_lrstd[k] + lbn[k];
        z = mu + expf(0.5f * lv) * eps[r * KT + k];
    }
    red[k] = z; __syncthreads();
    for (int off = 32; off > 0; off >>= 1) {
        if (k < off) red[k] = fmaxf(red[k], red[k + off]);
        __syncthreads();
    }
    float zm = red[0]; __syncthreads();
    float e = valid ? expf(z - zm) : 0.f;
    red[k] = e; __syncthreads();
    for (int off = 32; off > 0; off >>= 1) {
        if (k < off) red[k] += red[k + off];
        __syncthreads();
    }
    float Z = red[0]; __syncthreads();
    theta[r * KP + k] = e / Z;
    float term = valid ? (expf(lv) / var2 + mu * mu / var2 + logv2 - lv) : 0.f;
    red[k] = term; __syncthreads();
    for (int off = 32; off > 0; off >>= 1) {
        if (k < off) red[k] += red[k + off];
        __syncthreads();
    }
    if (k == 0) rowloss[r] = 0.5f * (red[0] - (float)KT);
}

__global__ void colstats_wide(const float* __restrict__ Y) {
    int c = (blockIdx.x << 6) + (threadIdx.x & 63);
    int g = threadIdx.x >> 6;
    float s1 = 0.f, s2 = 0.f;
    if (c < V) {
        for (int r = g; r < Bsz; r += 4) {
            float v = Y[(size_t)r * V + c];
            s1 += v; s2 = fmaf(v, v, s2);
        }
    }
    __shared__ float sh1[256], sh2[256];
    sh1[threadIdx.x] = s1; sh2[threadIdx.x] = s2; __syncthreads();
    if (g == 0 && c < V) {
        int t = threadIdx.x;
        float a1 = sh1[t] + sh1[t + 64] + sh1[t + 128] + sh1[t + 192];
        float a2 = sh2[t] + sh2[t + 64] + sh2[t + 128] + sh2[t + 192];
        float m = a1 / (float)Bsz;
        g_ymean[c] = m;
        g_yrstd[c] = rsqrtf(a2 / (float)Bsz - m * m + 1e-5f);
    }
}

__global__ void rec_kernel(
    const float* __restrict__ Y, const float* __restrict__ x,
    const float* __restrict__ dbias, float* __restrict__ rowloss)
{
    int r = blockIdx.x, t = threadIdx.x;
    __shared__ float red[256];
    float s[8];
    float lmax = -1e30f;
    #pragma unroll
    for (int i = 0; i < 8; i++) {
        int v = t + i * 256;
        if (v < V) {
            float val = (Y[(size_t)r * V + v] - g_ymean[v]) * g_yrstd[v] + dbias[v];
            s[i] = val; lmax = fmaxf(lmax, val);
        } else s[i] = -1e30f;
    }
    red[t] = lmax; __syncthreads();
    for (int off = 128; off > 0; off >>= 1) {
        if (t < off) red[t] = fmaxf(red[t], red[t + off]);
        __syncthreads();
    }
    float M = red[0]; __syncthreads();
    float ls = 0.f;
    #pragma unroll
    for (int i = 0; i < 8; i++) ls += expf(s[i] - M);
    red[t] = ls; __syncthreads();
    for (int off = 128; off > 0; off >>= 1) {
        if (t < off) red[t] += red[t + off];
        __syncthreads();
    }
    float invZ = 1.f / red[0]; __syncthreads();
    float acc = 0.f;
    #pragma unroll
    for (int i = 0; i < 8; i++) {
        int v = t + i * 256;
        if (v < V) {
            float p = expf(s[i] - M) * invZ;
            acc += x[(size_t)r * V + v] * logf(p + 1e-10f);
        }
    }
    red[t] = acc; __syncthreads();
    for (int off = 128; off > 0; off >>= 1) {
        if (t < off) red[t] += red[t + off];
        __syncthreads();
    }
    if (t == 0) rowloss[r] += -red[0];
}

__global__ void final_kernel(float* __restrict__ out) {
    int t = threadIdx.x;
    __shared__ float red[256];
    float sa = 0.f, sb = 0.f, sc = 0.f;
    for (int r = t; r < Bsz; r += 256) { sa += g_rowloss_a[r]; sb += g_rowloss_b[r]; }
    if (t < NBLK) sc = g_red[t];
    red[t] = sa; __syncthreads();
    for (int off = 128; off > 0; off >>= 1) { if (t < off) red[t] += red[t + off]; __syncthreads(); }
    float ta = red[0]; __syncthreads();
    red[t] = sb; __syncthreads();
    for (int off = 128; off > 0; off >>= 1) { if (t < off) red[t] += red[t + off]; __syncthreads(); }
    float tb = red[0]; __syncthreads();
    red[t] = sc; __syncthreads();
    for (int off = 128; off > 0; off >>= 1) { if (t < off) red[t] += red[t + off]; __syncthreads(); }
    if (t == 0) out[0] = ta / (float)Bsz + tb / (float)Bsz + 0.1f * red[0];
}

// ---------------- host ----------------
static float* sym(const void* s) {
    void* p = nullptr;
    cudaGetSymbolAddress(&p, s);
    return (float*)p;
}

extern "C" void kernel_launch(void* const* d_in, const int* in_sizes, int n_in,
                              void* d_out, int out_size) {
    const float* x_a  = (const float*)d_in[0];
    const float* x_b  = (const float*)d_in[1];
    const float* ep_a = (const float*)d_in[2];
    const float* ep_b = (const float*)d_in[3];
    const float* W1a = (const float*)d_in[4];  const float* b1a = (const float*)d_in[5];
    const float* W2a = (const float*)d_in[6];  const float* b2a = (const float*)d_in[7];
    const float* Wma = (const float*)d_in[8];  const float* bma = (const float*)d_in[9];
    const float* Wla = (const float*)d_in[10]; const float* bla = (const float*)d_in[11];
    const float* mbna = (const float*)d_in[12]; const float* lbna = (const float*)d_in[13];
    const float* W1b = (const float*)d_in[14]; const float* b1b = (const float*)d_in[15];
    const float* W2b = (const float*)d_in[16]; const float* b2b = (const float*)d_in[17];
    const float* Wmb = (const float*)d_in[18]; const float* bmb = (const float*)d_in[19];
    const float* Wlb = (const float*)d_in[20]; const float* blb = (const float*)d_in[21];
    const float* mbnb = (const float*)d_in[22]; const float* lbnb = (const float*)d_in[23];
    const float* dbn_a = (const float*)d_in[24]; const float* dbn_b = (const float*)d_in[25];
    const float* phi_a = (const float*)d_in[26]; const float* phi_b = (const float*)d_in[27];
    const float* bwe_a = (const float*)d_in[28]; const float* bwe_b = (const float*)d_in[29];

    float* h1 = sym(g_h1);   float* h2 = sym(g_h2);
    float* mulin = sym(g_mulin); float* lvlin = sym(g_lvlin);
    float* theta = sym(g_theta); float* Y = sym(g_Y);
    float* rla = sym(g_rowloss_a); float* rlb = sym(g_rowloss_b);
    float* mmean = sym(g_mmean); float* mrstd = sym(g_mrstd);
    float* lmean = sym(g_lmean); float* lrstd = sym(g_lrstd);
    float* na = sym(g_na); float* nb = sym(g_nb);
    float* pa = sym(g_a); float* pb = sym(g_b);

    static int smem_set = 0;
    if (!smem_set) {
        cudaFuncSetAttribute(sinkhorn_persist,
            cudaFuncAttributeMaxDynamicSharedMemorySize, SM_FLOATS * 4);
        smem_set = 1;
    }

    init_kernel<<<512, 256>>>();

    // ------ anchor branch ------
    sgemm_nn<<<dim3(8, 64), 256>>>(x_a, W1a, b1a, h1, Bsz, HID, V, V, HID, HID, 1);
    sgemm_nn<<<dim3(8, 64), 256>>>(h1, W2a, b2a, h2, Bsz, HID, HID, HID, HID, HID, 1);
    sgemm_nn<<<dim3(1, 64), 256>>>(h2, Wma, bma, mulin, Bsz, KT, HID, HID, KT, KP, 0);
    sgemm_nn<<<dim3(1, 64), 256>>>(h2, Wla, bla, lvlin, Bsz, KT, HID, HID, KT, KP, 0);
    colstats_narrow<<<KT, 256>>>(mulin, mmean, mrstd);
    colstats_narrow<<<KT, 256>>>(lvlin, lmean, lrstd);
    theta_kernel<<<Bsz, 64>>>(mulin, lvlin, mbna, lbna, ep_a, theta, rla);
    sgemm_nn<<<dim3(32, 64), 256>>>(theta, phi_a, nullptr, Y, Bsz, V, KT, KP, V, V, 0);
    colstats_wide<<<32, 256>>>(Y);
    rec_kernel<<<Bsz, 256>>>(Y, x_a, dbn_a, rla);

    // ------ alignment branch ------
    sgemm_nn<<<dim3(8, 64), 256>>>(x_b, W1b, b1b, h1, Bsz, HID, V, V, HID, HID, 1);
    sgemm_nn<<<dim3(8, 64), 256>>>(h1, W2b, b2b, h2, Bsz, HID, HID, HID, HID, HID, 1);
    sgemm_nn<<<dim3(1, 64), 256>>>(h2, Wmb, bmb, mulin, Bsz, KT, HID, HID, KT, KP, 0);
    sgemm_nn<<<dim3(1, 64), 256>>>(h2, Wlb, blb, lvlin, Bsz, KT, HID, HID, KT, KP, 0);
    colstats_narrow<<<KT, 256>>>(mulin, mmean, mrstd);
    colstats_narrow<<<KT, 256>>>(lvlin, lmean, lrstd);
    theta_kernel<<<Bsz, 64>>>(mulin, lvlin, mbnb, lbnb, ep_b, theta, rlb);
    sgemm_nn<<<dim3(32, 64), 256>>>(theta, phi_b, nullptr, Y, Bsz, V, KT, KP, V, V, 0);
    colstats_wide<<<32, 256>>>(Y);
    rec_kernel<<<Bsz, 256>>>(Y, x_b, dbn_b, rlb);

    // ------ Sinkhorn setup ------
    norm_rows<<<V, 128>>>(bwe_a, na);
    norm_rows<<<V, 128>>>(bwe_b, nb);
    cost_nt<<<dim3(32, 32), 256>>>(na, nb);
    colsoftmax<<<KT, 256>>>(phi_a, pa);
    colsoftmax<<<KT, 256>>>(phi_b, pb);

    // ------ Sinkhorn: single persistent launch (500 iters + final u + cost) ------
    sinkhorn_persist<<<NBLK, 512, SM_FLOATS * 4>>>();

    final_kernel<<<1, 256>>>((float*)d_out);
}

// round 11
// speedup vs baseline: 1.6169x; 1.6169x over previous
#include <cuda_runtime.h>
#include <math.h>

#define Bsz 4096
#define V 2000
#define VP 2048
#define KT 50
#define KP 64
#define HID 500
#define EMB 300

#define NBLK 128
#define RPB 16        // rows per block
#define NWARP 16      // 16 warps = 512 threads; warp w owns K-range w*128..+128
#define CHK 32        // kk staged per stage; 4 stages cover 128
#define AS_STR 36     // As row stride (32 kk + pad), 144B: 16B aligned
#define VSS 72        // Vs row stride (64 cols + pad), 288B: 16B aligned
#define AS_WARP (RPB*AS_STR)          // 576 floats
#define VS_WARP (CHK*VSS)             // 2304 floats
#define VS_BASE (NWARP*AS_WARP)       // 9216
#define SM_FLOATS (VS_BASE + NWARP*VS_WARP)   // 9216+36864 = 46080 floats (184320 B)

// ---------------- scratch (device globals; no runtime alloc) ----------------
__device__ float g_h1[Bsz*HID];
__device__ float g_h2[Bsz*HID];
__device__ float g_mulin[Bsz*KP];
__device__ float g_lvlin[Bsz*KP];
__device__ float g_theta[Bsz*KP];
__device__ float g_Y[Bsz*V];
__device__ float g_rowloss_a[Bsz];
__device__ float g_rowloss_b[Bsz];
__device__ float g_mmean[KP]; __device__ float g_mrstd[KP];
__device__ float g_lmean[KP]; __device__ float g_lrstd[KP];
__device__ float g_ymean[VP]; __device__ float g_yrstd[VP];
__device__ float g_na[V*EMB]; __device__ float g_nb[V*EMB];
__device__ float g_Km[VP*VP];
__device__ float g_KmT[VP*VP];
__device__ float g_KM[VP*VP];
__device__ float g_a[VP*KP]; __device__ float g_b[VP*KP];
__device__ float g_u[VP*KP]; __device__ float g_v[VP*KP];
__device__ float g_red[NBLK];
__device__ unsigned g_bar_cnt;
__device__ unsigned g_bar_gen;

// ---------------- f32x2 packed helpers ----------------
__device__ __forceinline__ unsigned long long pack2(float x) {
    unsigned long long r;
    asm("mov.b64 %0, {%1, %1};" : "=l"(r) : "f"(x));
    return r;
}
__device__ __forceinline__ void ffma2(unsigned long long& d,
                                      unsigned long long a, unsigned long long b) {
    asm("fma.rn.f32x2 %0, %1, %2, %0;" : "+l"(d) : "l"(a), "l"(b));
}

// ---------------- generic NN SGEMM: C = act(A@B + bias) ----------------
__global__ __launch_bounds__(256) void sgemm_nn(
    const float* __restrict__ A, const float* __restrict__ B,
    const float* __restrict__ bias, float* __restrict__ C,
    int M, int N, int K, int lda, int ldb, int ldc, int act)
{
    __shared__ float As[16][68];
    __shared__ float Bs[16][68];
    int tid = threadIdx.x;
    int tx = tid & 15, ty = tid >> 4;
    int row0 = blockIdx.y * 64, col0 = blockIdx.x * 64;
    float acc[4][4];
    #pragma unroll
    for (int i = 0; i < 4; i++)
        #pragma unroll
        for (int j = 0; j < 4; j++) acc[i][j] = 0.f;

    for (int k0 = 0; k0 < K; k0 += 16) {
        #pragma unroll
        for (int s = 0; s < 4; s++) {
            int idx = tid + s * 256;
            int m = idx >> 4, kk = idx & 15;
            int gr = row0 + m, gk = k0 + kk;
            As[kk][m] = (gr < M && gk < K) ? A[(size_t)gr * lda + gk] : 0.f;
        }
        #pragma unroll
        for (int s = 0; s < 4; s++) {
            int idx = tid + s * 256;
            int kk = idx >> 6, n = idx & 63;
            int gk = k0 + kk, gc = col0 + n;
            Bs[kk][n] = (gk < K && gc < N) ? B[(size_t)gk * ldb + gc] : 0.f;
        }
        __syncthreads();
        #pragma unroll
        for (int kk = 0; kk < 16; kk++) {
            float ra[4], rb[4];
            #pragma unroll
            for (int i = 0; i < 4; i++) ra[i] = As[kk][ty * 4 + i];
            #pragma unroll
            for (int j = 0; j < 4; j++) rb[j] = Bs[kk][tx * 4 + j];
            #pragma unroll
            for (int i = 0; i < 4; i++)
                #pragma unroll
                for (int j = 0; j < 4; j++)
                    acc[i][j] = fmaf(ra[i], rb[j], acc[i][j]);
        }
        __syncthreads();
    }
    #pragma unroll
    for (int i = 0; i < 4; i++) {
        int gr = row0 + ty * 4 + i;
        if (gr >= M) continue;
        #pragma unroll
        for (int j = 0; j < 4; j++) {
            int gc = col0 + tx * 4 + j;
            if (gc >= N) continue;
            float vv = acc[i][j];
            if (bias) vv += bias[gc];
            if (act) vv = fmaxf(vv, 0.f) + log1pf(expf(-fabsf(vv)));
            C[(size_t)gr * ldc + gc] = vv;
        }
    }
}

// ---------------- persistent Sinkhorn ----------------
__device__ __forceinline__ void grid_barrier() {
    __syncthreads();
    if (threadIdx.x == 0) {
        __threadfence();
        unsigned gen = *(volatile unsigned*)&g_bar_gen;
        if (atomicAdd(&g_bar_cnt, 1u) == NBLK - 1u) {
            *(volatile unsigned*)&g_bar_cnt = 0u;
            __threadfence();
            *(volatile unsigned*)&g_bar_gen = gen + 1u;
        } else {
            while (*(volatile unsigned*)&g_bar_gen == gen) __nanosleep(32);
        }
        __threadfence();
    }
    __syncthreads();
}

// warp w: acc2[4][4] += A[r0..r0+16, w*128..+128] @ x[w*128..+128, 0..64]
// coalesced staging: x slice is contiguous; A rows loaded 4-per-warp-LDG.
__device__ __forceinline__ void tile_mm2(
    const float* __restrict__ A, const float* __restrict__ x,
    float* sm, int r0, int w, int lane, int r4, int c8,
    unsigned long long acc2[4][4])
{
    float* As = sm + w * AS_WARP;
    float* Vs = sm + VS_BASE + w * VS_WARP;
    #pragma unroll
    for (int s = 0; s < 4; s++) {
        int k0 = w * 128 + s * CHK;
        // stage A: 16 rows x 32 cols = 128 float4; lanes sequential within rows
        #pragma unroll
        for (int q = 0; q < 4; q++) {
            int f4 = q * 32 + lane;
            int row = f4 >> 3, c4 = f4 & 7;
            float4 val = __ldg((const float4*)&A[(size_t)(r0 + row) * VP + k0] + c4);
            *(float4*)&As[row * AS_STR + c4 * 4] = val;
        }
        // stage x: contiguous 8KB block (32 k-rows x 64 cols) = 512 float4
        const float4* xb = (const float4*)&x[(size_t)k0 * KP];
        #pragma unroll
        for (int q = 0; q < 16; q++) {
            int f4 = q * 32 + lane;
            int row = f4 >> 4, c4 = f4 & 15;
            float4 val = __ldcg(xb + f4);
            *(float4*)&Vs[row * VSS + c4 * 4] = val;
        }
        __syncwarp();
        #pragma unroll
        for (int kk = 0; kk < CHK; kk++) {
            float a0 = As[(r4 * 4 + 0) * AS_STR + kk];
            float a1 = As[(r4 * 4 + 1) * AS_STR + kk];
            float a2 = As[(r4 * 4 + 2) * AS_STR + kk];
            float a3 = As[(r4 * 4 + 3) * AS_STR + kk];
            const ulonglong2* bp = (const ulonglong2*)&Vs[kk * VSS + c8 * 8];
            ulonglong2 b01 = bp[0], b23 = bp[1];
            unsigned long long rb[4] = {b01.x, b01.y, b23.x, b23.y};
            unsigned long long ap;
            ap = pack2(a0);
            #pragma unroll
            for (int j = 0; j < 4; j++) ffma2(acc2[0][j], ap, rb[j]);
            ap = pack2(a1);
            #pragma unroll
            for (int j = 0; j < 4; j++) ffma2(acc2[1][j], ap, rb[j]);
            ap = pack2(a2);
            #pragma unroll
            for (int j = 0; j < 4; j++) ffma2(acc2[2][j], ap, rb[j]);
            ap = pack2(a3);
            #pragma unroll
            for (int j = 0; j < 4; j++) ffma2(acc2[3][j], ap, rb[j]);
        }
        __syncwarp();
    }
}

__device__ __forceinline__ void store_partials2(
    float* red, unsigned long long acc2[4][4], int w, int r4, int c8)
{
    #pragma unroll
    for (int i = 0; i < 4; i++) {
        ulonglong2* dst = (ulonglong2*)&red[w * 1024 + (r4 * 4 + i) * 64 + c8 * 8];
        dst[0] = make_ulonglong2(acc2[i][0], acc2[i][1]);
        dst[1] = make_ulonglong2(acc2[i][2], acc2[i][3]);
    }
}

__global__ __launch_bounds__(512, 1) void sinkhorn_persist() {
    extern __shared__ float sm[];
    int t = threadIdx.x;
    int w = t >> 5, lane = t & 31;
    int r4 = lane >> 3, c8 = lane & 7;
    int r0 = blockIdx.x * RPB;
    float* red = sm;  // alias of As/Vs (guarded by __syncthreads)

    for (int half = 0; half < 2 * 500 + 1; half++) {
        bool uh = !(half & 1);
        const float* A = uh ? g_Km : g_KmT;
        const float* x = uh ? g_v : g_u;
        const float* num = uh ? g_a : g_b;
        float* out = uh ? g_u : g_v;

        unsigned long long acc2[4][4];
        #pragma unroll
        for (int i = 0; i < 4; i++)
            #pragma unroll
            for (int j = 0; j < 4; j++) acc2[i][j] = 0ULL;

        tile_mm2(A, x, sm, r0, w, lane, r4, c8, acc2);
        __syncthreads();                      // all FMA reads done before red alias
        store_partials2(red, acc2, w, r4, c8);
        __syncthreads();
        {
            int oi = t * 2;                   // 1024 outputs, float2 each thread
            float sx = 0.f, sy = 0.f;
            #pragma unroll
            for (int gg = 0; gg < NWARP; gg++) {
                float2 p = *(const float2*)&red[gg * 1024 + oi];
                sx += p.x; sy += p.y;
            }
            int row = oi >> 6, col = oi & 63;
            float2 nm = *(const float2*)&num[(size_t)(r0 + row) * KP + col];
            float2 uv;
            uv.x = nm.x / (sx + 1e-16f);
            uv.y = nm.y / (sy + 1e-16f);
            *(float2*)&out[(size_t)(r0 + row) * KP + col] = uv;
        }
        grid_barrier();                       // includes leading __syncthreads
    }

    // epilogue: s = (Km*M) @ v ; cost partial = sum(u * s) over block rows
    unsigned long long acc2[4][4];
    #pragma unroll
    for (int i = 0; i < 4; i++)
        #pragma unroll
        for (int j = 0; j < 4; j++) acc2[i][j] = 0ULL;
    tile_mm2(g_KM, g_v, sm, r0, w, lane, r4, c8, acc2);
    __syncthreads();
    store_partials2(red, acc2, w, r4, c8);
    __syncthreads();
    float part = 0.f;
    {
        int oi = t * 2;
        float sx = 0.f, sy = 0.f;
        #pragma unroll
        for (int gg = 0; gg < NWARP; gg++) {
            float2 p = *(const float2*)&red[gg * 1024 + oi];
            sx += p.x; sy += p.y;
        }
        int row = oi >> 6, col = oi & 63;
        float2 uu = *(const float2*)&g_u[(size_t)(r0 + row) * KP + col];
        part = fmaf(uu.x, sx, fmaf(uu.y, sy, 0.f));
    }
    __syncthreads();
    red[t] = part; __syncthreads();
    for (int off = 256; off > 0; off >>= 1) {
        if (t < off) red[t] += red[t + off];
        __syncthreads();
    }
    if (t == 0) g_red[blockIdx.x] = red[0];
}

__global__ void init_kernel() {
    int idx = blockIdx.x * 256 + threadIdx.x;
    if (idx == 0) { g_bar_cnt = 0u; g_bar_gen = 0u; }
    g_a[idx] = 0.f; g_b[idx] = 0.f;
    int i = idx >> 6, k = idx & 63;
    g_v[idx] = (i < V && k < KT) ? (1.f / V) : 0.f;
}

// per-column softmax over V rows of BOTH phis: grid (KT, 2)
__global__ void colsoftmax2(const float* __restrict__ phiA, float* __restrict__ outA,
                            const float* __restrict__ phiB, float* __restrict__ outB) {
    int k = blockIdx.x, t = threadIdx.x;
    const float* phi = blockIdx.y ? phiB : phiA;
    float* out = blockIdx.y ? outB : outA;
    const float* col = phi + (size_t)k * V;
    __shared__ float red[256];
    float m = -1e30f;
    for (int i = t; i < V; i += 256) m = fmaxf(m, col[i]);
    red[t] = m; __syncthreads();
    for (int off = 128; off > 0; off >>= 1) {
        if (t < off) red[t] = fmaxf(red[t], red[t + off]);
        __syncthreads();
    }
    float mx = red[0]; __syncthreads();
    float s = 0.f;
    for (int i = t; i < V; i += 256) s += expf(col[i] - mx);
    red[t] = s; __syncthreads();
    for (int off = 128; off > 0; off >>= 1) {
        if (t < off) red[t] += red[t + off];
        __syncthreads();
    }
    float inv = 1.f / red[0];
    for (int i = t; i < V; i += 256) out[i * KP + k] = expf(col[i] - mx) * inv;
}

__global__ void norm_rows(const float* __restrict__ Bm, float* __restrict__ out) {
    int r = blockIdx.x, t = threadIdx.x;
    __shared__ float red[128];
    float s = 0.f;
    for (int e = t; e < EMB; e += 128) { float v = Bm[r * EMB + e]; s = fmaf(v, v, s); }
    red[t] = s; __syncthreads();
    for (int off = 64; off > 0; off >>= 1) {
        if (t < off) red[t] += red[t + off];
        __syncthreads();
    }
    float sc = 1.f / fmaxf(sqrtf(red[0]), 1e-12f);
    for (int e = t; e < EMB; e += 128) out[r * EMB + e] = Bm[r * EMB + e] * sc;
}

__global__ __launch_bounds__(256) void cost_nt(
    const float* __restrict__ na, const float* __restrict__ nb)
{
    __shared__ float As[8][68];
    __shared__ float Bs[8][68];
    int tid = threadIdx.x, tx = tid & 15, ty = tid >> 4;
    int i0 = blockIdx.y * 64, j0 = blockIdx.x * 64;
    float acc[4][4];
    #pragma unroll
    for (int i = 0; i < 4; i++)
        #pragma unroll
        for (int j = 0; j < 4; j++) acc[i][j] = 0.f;

    for (int k0 = 0; k0 < 304; k0 += 8) {
        #pragma unroll
        for (int s = 0; s < 2; s++) {
            int idx = tid + s * 256;
            int m = idx >> 3, kk = idx & 7;
            int gk = k0 + kk;
            int gi = i0 + m;
            As[kk][m] = (gi < V && gk < EMB) ? na[(size_t)gi * EMB + gk] : 0.f;
            int gj = j0 + m;
            Bs[kk][m] = (gj < V && gk < EMB) ? nb[(size_t)gj * EMB + gk] : 0.f;
        }
        __syncthreads();
        #pragma unroll
        for (int kk = 0; kk < 8; kk++) {
            float ra[4], rb[4];
            #pragma unroll
            for (int i = 0; i < 4; i++) ra[i] = As[kk][ty * 4 + i];
            #pragma unroll
            for (int j = 0; j < 4; j++) rb[j] = Bs[kk][tx * 4 + j];
            #pragma unroll
            for (int i = 0; i < 4; i++)
                #pragma unroll
                for (int j = 0; j < 4; j++)
                    acc[i][j] = fmaf(ra[i], rb[j], acc[i][j]);
        }
        __syncthreads();
    }
    #pragma unroll
    for (int i = 0; i < 4; i++) {
        #pragma unroll
        for (int j = 0; j < 4; j++) {
            int gi = i0 + ty * 4 + i, gj = j0 + tx * 4 + j;
            float km = 0.f, kmm = 0.f;
            if (gi < V && gj < V) {
                float m = 1.f - acc[i][j];
                km = expf(-10.f * m);
                kmm = km * m;
            }
            g_Km[(size_t)gi * VP + gj] = km;
            g_KmT[(size_t)gj * VP + gi] = km;
            g_KM[(size_t)gi * VP + gj] = kmm;
        }
    }
}

__global__ void colstats_narrow(const float* __restrict__ X, float* mean, float* rstd) {
    int c = blockIdx.x, t = threadIdx.x;
    __shared__ float s1[256], s2[256];
    float a1 = 0.f, a2 = 0.f;
    for (int r = t; r < Bsz; r += 256) {
        float v = X[r * KP + c];
        a1 += v; a2 = fmaf(v, v, a2);
    }
    s1[t] = a1; s2[t] = a2; __syncthreads();
    for (int off = 128; off > 0; off >>= 1) {
        if (t < off) { s1[t] += s1[t + off]; s2[t] += s2[t + off]; }
        __syncthreads();
    }
    if (t == 0) {
        float m = s1[0] / (float)Bsz;
        mean[c] = m;
        rstd[c] = rsqrtf(s2[0] / (float)Bsz - m * m + 1e-5f);
    }
}

__global__ void theta_kernel(
    const float* __restrict__ mulin, const float* __restrict__ lvlin,
    const float* __restrict__ mbn, const float* __restrict__ lbn,
    const float* __restrict__ eps, float* __restrict__ theta, float* __restrict__ rowloss)
{
    int r = blockIdx.x, k = threadIdx.x;
    __shared__ float red[64];
    const float var2 = 0.98f;
    const float logv2 = -0.0202027073f;
    bool valid = (k < KT);
    float mu = 0.f, lv = 0.f, z = -1e30f;
    if (valid) {
        mu = (mulin[r * KP + k] - g_mmean[k]) * g_mrstd[k] + mbn[k];
        lv = (lvlin[r * KP + k] - g_lmean[k]) * g_lrstd[k] + lbn[k];
        z = mu + expf(0.5f * lv) * eps[r * KT + k];
    }
    red[k] = z; __syncthreads();
    for (int off = 32; off > 0; off >>= 1) {
        if (k < off) red[k] = fmaxf(red[k], red[k + off]);
        __syncthreads();
    }
    float zm = red[0]; __syncthreads();
    float e = valid ? expf(z - zm) : 0.f;
    red[k] = e; __syncthreads();
    for (int off = 32; off > 0; off >>= 1) {
        if (k < off) red[k] += red[k + off];
        __syncthreads();
    }
    float Z = red[0]; __syncthreads();
    theta[r * KP + k] = e / Z;
    float term = valid ? (expf(lv) / var2 + mu * mu / var2 + logv2 - lv) : 0.f;
    red[k] = term; __syncthreads();
    for (int off = 32; off > 0; off >>= 1) {
        if (k < off) red[k] += red[k + off];
        __syncthreads();
    }
    if (k == 0) rowloss[r] = 0.5f * (red[0] - (float)KT);
}

__global__ void colstats_wide(const float* __restrict__ Y) {
    int c = (blockIdx.x << 6) + (threadIdx.x & 63);
    int g = threadIdx.x >> 6;
    float s1 = 0.f, s2 = 0.f;
    if (c < V) {
        for (int r = g; r < Bsz; r += 4) {
            float v = Y[(size_t)r * V + c];
            s1 += v; s2 = fmaf(v, v, s2);
        }
    }
    __shared__ float sh1[256], sh2[256];
    sh1[threadIdx.x] = s1; sh2[threadIdx.x] = s2; __syncthreads();
    if (g == 0 && c < V) {
        int t = threadIdx.x;
        float a1 = sh1[t] + sh1[t + 64] + sh1[t + 128] + sh1[t + 192];
        float a2 = sh2[t] + sh2[t + 64] + sh2[t + 128] + sh2[t + 192];
        float m = a1 / (float)Bsz;
        g_ymean[c] = m;
        g_yrstd[c] = rsqrtf(a2 / (float)Bsz - m * m + 1e-5f);
    }
}

__global__ void rec_kernel(
    const float* __restrict__ Y, const float* __restrict__ x,
    const float* __restrict__ dbias, float* __restrict__ rowloss)
{
    int r = blockIdx.x, t = threadIdx.x;
    __shared__ float red[256];
    float s[8];
    float lmax = -1e30f;
    #pragma unroll
    for (int i = 0; i < 8; i++) {
        int v = t + i * 256;
        if (v < V) {
            float val = (Y[(size_t)r * V + v] - g_ymean[v]) * g_yrstd[v] + dbias[v];
            s[i] = val; lmax = fmaxf(lmax, val);
        } else s[i] = -1e30f;
    }
    red[t] = lmax; __syncthreads();
    for (int off = 128; off > 0; off >>= 1) {
        if (t < off) red[t] = fmaxf(red[t], red[t + off]);
        __syncthreads();
    }
    float M = red[0]; __syncthreads();
    float ls = 0.f;
    #pragma unroll
    for (int i = 0; i < 8; i++) ls += expf(s[i] - M);
    red[t] = ls; __syncthreads();
    for (int off = 128; off > 0; off >>= 1) {
        if (t < off) red[t] += red[t + off];
        __syncthreads();
    }
    float invZ = 1.f / red[0]; __syncthreads();
    float acc = 0.f;
    #pragma unroll
    for (int i = 0; i < 8; i++) {
        int v = t + i * 256;
        if (v < V) {
            float p = expf(s[i] - M) * invZ;
            acc += x[(size_t)r * V + v] * logf(p + 1e-10f);
        }
    }
    red[t] = acc; __syncthreads();
    for (int off = 128; off > 0; off >>= 1) {
        if (t < off) red[t] += red[t + off];
        __syncthreads();
    }
    if (t == 0) rowloss[r] += -red[0];
}

__global__ void final_kernel(float* __restrict__ out) {
    int t = threadIdx.x;
    __shared__ float red[256];
    float sa = 0.f, sb = 0.f, sc = 0.f;
    for (int r = t; r < Bsz; r += 256) { sa += g_rowloss_a[r]; sb += g_rowloss_b[r]; }
    if (t < NBLK) sc = g_red[t];
    red[t] = sa; __syncthreads();
    for (int off = 128; off > 0; off >>= 1) { if (t < off) red[t] += red[t + off]; __syncthreads(); }
    float ta = red[0]; __syncthreads();
    red[t] = sb; __syncthreads();
    for (int off = 128; off > 0; off >>= 1) { if (t < off) red[t] += red[t + off]; __syncthreads(); }
    float tb = red[0]; __syncthreads();
    red[t] = sc; __syncthreads();
    for (int off = 128; off > 0; off >>= 1) { if (t < off) red[t] += red[t + off]; __syncthreads(); }
    if (t == 0) out[0] = ta / (float)Bsz + tb / (float)Bsz + 0.1f * red[0];
}

// ---------------- host ----------------
static float* sym(const void* s) {
    void* p = nullptr;
    cudaGetSymbolAddress(&p, s);
    return (float*)p;
}

extern "C" void kernel_launch(void* const* d_in, const int* in_sizes, int n_in,
                              void* d_out, int out_size) {
    const float* x_a  = (const float*)d_in[0];
    const float* x_b  = (const float*)d_in[1];
    const float* ep_a = (const float*)d_in[2];
    const float* ep_b = (const float*)d_in[3];
    const float* W1a = (const float*)d_in[4];  const float* b1a = (const float*)d_in[5];
    const float* W2a = (const float*)d_in[6];  const float* b2a = (const float*)d_in[7];
    const float* Wma = (const float*)d_in[8];  const float* bma = (const float*)d_in[9];
    const float* Wla = (const float*)d_in[10]; const float* bla = (const float*)d_in[11];
    const float* mbna = (const float*)d_in[12]; const float* lbna = (const float*)d_in[13];
    const float* W1b = (const float*)d_in[14]; const float* b1b = (const float*)d_in[15];
    const float* W2b = (const float*)d_in[16]; const float* b2b = (const float*)d_in[17];
    const float* Wmb = (const float*)d_in[18]; const float* bmb = (const float*)d_in[19];
    const float* Wlb = (const float*)d_in[20]; const float* blb = (const float*)d_in[21];
    const float* mbnb = (const float*)d_in[22]; const float* lbnb = (const float*)d_in[23];
    const float* dbn_a = (const float*)d_in[24]; const float* dbn_b = (const float*)d_in[25];
    const float* phi_a = (const float*)d_in[26]; const float* phi_b = (const float*)d_in[27];
    const float* bwe_a = (const float*)d_in[28]; const float* bwe_b = (const float*)d_in[29];

    float* h1 = sym(g_h1);   float* h2 = sym(g_h2);
    float* mulin = sym(g_mulin); float* lvlin = sym(g_lvlin);
    float* theta = sym(g_theta); float* Y = sym(g_Y);
    float* rla = sym(g_rowloss_a); float* rlb = sym(g_rowloss_b);
    float* mmean = sym(g_mmean); float* mrstd = sym(g_mrstd);
    float* lmean = sym(g_lmean); float* lrstd = sym(g_lrstd);
    float* na = sym(g_na); float* nb = sym(g_nb);
    float* pa = sym(g_a); float* pb = sym(g_b);

    static int smem_set = 0;
    if (!smem_set) {
        cudaFuncSetAttribute(sinkhorn_persist,
            cudaFuncAttributeMaxDynamicSharedMemorySize, SM_FLOATS * 4);
        smem_set = 1;
    }

    // ------ Sinkhorn first (launch #5 = sinkhorn_persist for ncu -s 5) ------
    init_kernel<<<512, 256>>>();                               // 0
    norm_rows<<<V, 128>>>(bwe_a, na);                          // 1
    norm_rows<<<V, 128>>>(bwe_b, nb);                          // 2
    cost_nt<<<dim3(32, 32), 256>>>(na, nb);                    // 3
    colsoftmax2<<<dim3(KT, 2), 256>>>(phi_a, pa, phi_b, pb);   // 4
    sinkhorn_persist<<<NBLK, 512, SM_FLOATS * 4>>>();          // 5  <- profiled

    // ------ anchor branch ------
    sgemm_nn<<<dim3(8, 64), 256>>>(x_a, W1a, b1a, h1, Bsz, HID, V, V, HID, HID, 1);
    sgemm_nn<<<dim3(8, 64), 256>>>(h1, W2a, b2a, h2, Bsz, HID, HID, HID, HID, HID, 1);
    sgemm_nn<<<dim3(1, 64), 256>>>(h2, Wma, bma, mulin, Bsz, KT, HID, HID, KT, KP, 0);
    sgemm_nn<<<dim3(1, 64), 256>>>(h2, Wla, bla, lvlin, Bsz, KT, HID, HID, KT, KP, 0);
    colstats_narrow<<<KT, 256>>>(mulin, mmean, mrstd);
    colstats_narrow<<<KT, 256>>>(lvlin, lmean, lrstd);
    theta_kernel<<<Bsz, 64>>>(mulin, lvlin, mbna, lbna, ep_a, theta, rla);
    sgemm_nn<<<dim3(32, 64), 256>>>(theta, phi_a, nullptr, Y, Bsz, V, KT, KP, V, V, 0);
    colstats_wide<<<32, 256>>>(Y);
    rec_kernel<<<Bsz, 256>>>(Y, x_a, dbn_a, rla);

    // ------ alignment branch ------
    sgemm_nn<<<dim3(8, 64), 256>>>(x_b, W1b, b1b, h1, Bsz, HID, V, V, HID, HID, 1);
    sgemm_nn<<<dim3(8, 64), 256>>>(h1, W2b, b2b, h2, Bsz, HID, HID, HID, HID, HID, 1);
    sgemm_nn<<<dim3(1, 64), 256>>>(h2, Wmb, bmb, mulin, Bsz, KT, HID, HID, KT, KP, 0);
    sgemm_nn<<<dim3(1, 64), 256>>>(h2, Wlb, blb, lvlin, Bsz, KT, HID, HID, KT, KP, 0);
    colstats_narrow<<<KT, 256>>>(mulin, mmean, mrstd);
    colstats_narrow<<<KT, 256>>>(lvlin, lmean, lrstd);
    theta_kernel<<<Bsz, 64>>>(mulin, lvlin, mbnb, lbnb, ep_b, theta, rlb);
    sgemm_nn<<<dim3(32, 64), 256>>>(theta, phi_b, nullptr, Y, Bsz, V, KT, KP, V, V, 0);
    colstats_wide<<<32, 256>>>(Y);
    rec_kernel<<<Bsz, 256>>>(Y, x_b, dbn_b, rlb);

    final_kernel<<<1, 256>>>((float*)d_out);
}